// round 14
// baseline (speedup 1.0000x reference)
#include <cuda_runtime.h>
#include <cuda_bf16.h>

#define Bsz 512
#define Ssz 512
#define Dsz 64
#define Hsz 128
#define Gsz 512

// ---- LSTM v6 smem layout (bytes) ----
#define KSMH 32
#define KREGH 32
#define WSM_SLICES 64
#define HD_OFF   (WSM_SLICES*2048)       // 131072
#define PART_OFF (HD_OFF + 4096)
#define LSTM6_SMEM (PART_OFF + 8192)     // 143360

// ---- MMA GEMM smem: tile 128x64, images padded rows of 144B ----
#define SP_ROW 144
#define AH_OFF 0
#define AL_OFF 18432
#define BH_OFF 36864
#define BL_OFF 46080
#define GEMM_SMEM 55296

typedef unsigned long long u64;
typedef unsigned int u32;

__device__ float g_pre[(size_t)Bsz * Ssz * Gsz];
__device__ float g_h2last[Bsz * Hsz];
__device__ float g_whh_t[2 * Hsz * Gsz];
__device__ float g_bias[2 * Gsz];
// bf16 hi/lo images (u32 = pair of bf16 along k)
__device__ u32 g_b0h[512 * 32], g_b0l[512 * 32];           // W_ih0 [n][k] K=64
__device__ u32 g_b1h[512 * 64], g_b1l[512 * 64];           // W_ih1 [n][k] K=128
__device__ u32 g_a0h[(size_t)Bsz * Ssz * 32];              // x split, K=64
__device__ u32 g_a0l[(size_t)Bsz * Ssz * 32];
__device__ u32 g_a1h[(size_t)Bsz * Ssz * 64];              // h1 split, K=128
__device__ u32 g_a1l[(size_t)Bsz * Ssz * 64];

__device__ __forceinline__ u64 pack2(float x, float y) {
    u64 r; asm("mov.b64 %0, {%1,%2};" : "=l"(r) : "f"(x), "f"(y)); return r;
}
__device__ __forceinline__ void unpack2(u64 v, float &x, float &y) {
    asm("mov.b64 {%0,%1}, %2;" : "=f"(x), "=f"(y) : "l"(v));
}
__device__ __forceinline__ u64 ffma2(u64 a, u64 b, u64 c) {
    u64 d; asm("fma.rn.f32x2 %0, %1, %2, %3;" : "=l"(d) : "l"(a), "l"(b), "l"(c));
    return d;
}
__device__ __forceinline__ u64 addf2(u64 a, u64 b) {
    u64 d; asm("add.rn.f32x2 %0, %1, %2;" : "=l"(d) : "l"(a), "l"(b));
    return d;
}
__device__ __forceinline__ u32 smem_u32(const void* p) {
    u32 a; asm("{ .reg .u64 t; cvta.to.shared.u64 t, %1; cvt.u32.u64 %0, t; }" : "=r"(a) : "l"(p));
    return a;
}
__device__ __forceinline__ void lds_v2(u32 a, u64 &x, u64 &y) {
    asm volatile("ld.shared.v2.u64 {%0,%1}, [%2];" : "=l"(x), "=l"(y) : "r"(a));
}
__device__ __forceinline__ u64 lds_64(u32 a) {
    u64 x; asm volatile("ld.shared.u64 %0, [%1];" : "=l"(x) : "r"(a)); return x;
}
__device__ __forceinline__ void sts_v2(u32 a, u64 x, u64 y) {
    asm volatile("st.shared.v2.u64 [%0], {%1,%2};" :: "r"(a), "l"(x), "l"(y));
}
__device__ __forceinline__ void sts_64(u32 a, u64 x) {
    asm volatile("st.shared.u64 [%0], %1;" :: "r"(a), "l"(x));
}
__device__ __forceinline__ void sts_v4u32(u32 a, u32 x, u32 y, u32 z, u32 w) {
    asm volatile("st.shared.v4.u32 [%0], {%1,%2,%3,%4};" :: "r"(a), "r"(x), "r"(y), "r"(z), "r"(w));
}
__device__ __forceinline__ float tanh_fast(float x) {
    float y; asm("tanh.approx.f32 %0, %1;" : "=f"(y) : "f"(x)); return y;
}
__device__ __forceinline__ float sig_fast(float x) {
    return fmaf(tanh_fast(0.5f * x), 0.5f, 0.5f);
}
__device__ __forceinline__ void ldmx4(u32 addr, u32 &r0, u32 &r1, u32 &r2, u32 &r3) {
    asm volatile("ldmatrix.sync.aligned.m8n8.x4.shared.b16 {%0,%1,%2,%3}, [%4];"
                 : "=r"(r0), "=r"(r1), "=r"(r2), "=r"(r3) : "r"(addr));
}
__device__ __forceinline__ void mma_bf16(float* c, const u32* a, u32 b0, u32 b1) {
    asm volatile(
        "mma.sync.aligned.m16n8k16.row.col.f32.bf16.bf16.f32 "
        "{%0,%1,%2,%3}, {%4,%5,%6,%7}, {%8,%9}, {%0,%1,%2,%3};"
        : "+f"(c[0]), "+f"(c[1]), "+f"(c[2]), "+f"(c[3])
        : "r"(a[0]), "r"(a[1]), "r"(a[2]), "r"(a[3]), "r"(b0), "r"(b1));
}
__device__ __forceinline__ void bf16split(float v0, float v1, u32 &hi, u32 &lo) {
    __nv_bfloat16 h0 = __float2bfloat16(v0);
    __nv_bfloat16 h1 = __float2bfloat16(v1);
    float r0 = v0 - __bfloat162float(h0);
    float r1 = v1 - __bfloat162float(h1);
    __nv_bfloat162 hp; hp.x = h0; hp.y = h1;
    __nv_bfloat162 lp; lp.x = __float2bfloat16(r0); lp.y = __float2bfloat16(r1);
    hi = *reinterpret_cast<u32*>(&hp);
    lo = *reinterpret_cast<u32*>(&lp);
}

// --------------------------------- prep -------------------------------------
__global__ void prep_kernel(const float* __restrict__ x,
                            const float* __restrict__ Wih0, const float* __restrict__ Whh0,
                            const float* __restrict__ bih0, const float* __restrict__ bhh0,
                            const float* __restrict__ Wih1, const float* __restrict__ Whh1,
                            const float* __restrict__ bih1, const float* __restrict__ bhh1) {
    int tid = blockIdx.x * blockDim.x + threadIdx.x;
    int nt  = gridDim.x * blockDim.x;
    for (int idx = tid; idx < Hsz * Gsz; idx += nt) {
        int k = idx >> 9;
        int jg = idx & 511;
        int j = jg >> 2, g = jg & 3;
        g_whh_t[idx]             = Whh0[(g * Hsz + j) * Hsz + k];
        g_whh_t[Hsz * Gsz + idx] = Whh1[(g * Hsz + j) * Hsz + k];
        if (idx < Gsz) {
            g_bias[idx]       = bih0[idx] + bhh0[idx];
            g_bias[Gsz + idx] = bih1[idx] + bhh1[idx];
        }
    }
    for (int i = tid; i < 512 * 32; i += nt) {
        int n = i >> 5, kp = i & 31;
        u32 hi, lo;
        bf16split(Wih0[n * 64 + 2 * kp], Wih0[n * 64 + 2 * kp + 1], hi, lo);
        g_b0h[i] = hi; g_b0l[i] = lo;
    }
    for (int i = tid; i < 512 * 64; i += nt) {
        int n = i >> 6, kp = i & 63;
        u32 hi, lo;
        bf16split(Wih1[n * 128 + 2 * kp], Wih1[n * 128 + 2 * kp + 1], hi, lo);
        g_b1h[i] = hi; g_b1l[i] = lo;
    }
    // split x -> A0 images (row = b*S+s, 32 u32 pairs per row)
    for (size_t i = tid; i < (size_t)Bsz * Ssz * 32; i += nt) {
        size_t r = i >> 5;
        int kp = (int)(i & 31);
        const float* xr = x + r * 64 + 2 * kp;
        u32 hi, lo;
        bf16split(xr[0], xr[1], hi, lo);
        g_a0h[i] = hi; g_a0l[i] = lo;
    }
}

// ---------------- mma.sync pre GEMM: image A + image B, tile 128x64 ----------
// grid: x = nb (N/64), y = mb (BS/128) -> consecutive CTAs share A (L2 reuse)
template <int K>
__global__ __launch_bounds__(256, 2) void gemm_mma_kernel(
    const u32* __restrict__ Ah_img, const u32* __restrict__ Al_img,
    const u32* __restrict__ Bh_img, const u32* __restrict__ Bl_img,
    const float* __restrict__ bias, float* __restrict__ C) {
    extern __shared__ char smc[];
    u32 sb = smem_u32(smc);
    int tid = threadIdx.x, lane = tid & 31, wid = tid >> 5;
    int wm = wid & 3, wn = wid >> 2;
    int nb = blockIdx.x, mb = blockIdx.y;

    float acc[2][4][4];
#pragma unroll
    for (int mt = 0; mt < 2; ++mt)
#pragma unroll
        for (int nt = 0; nt < 4; ++nt)
#pragma unroll
            for (int e = 0; e < 4; ++e) acc[mt][nt][e] = 0.f;

    const int NCH = K / 64;
#pragma unroll
    for (int ch = 0; ch < NCH; ++ch) {
        if (ch) __syncthreads();
        // A chunk: 128 rows x 8 uint4 (pre-split images)
#pragma unroll
        for (int it = 0; it < 4; ++it) {
            int f = tid + it * 256;
            int r = f >> 3, u4 = f & 7;
            size_t gi = (size_t)(mb * 128 + r) * (K / 2) + ch * 32 + u4 * 4;
            uint4 vh = *(const uint4*)(Ah_img + gi);
            uint4 vl = *(const uint4*)(Al_img + gi);
            u32 off = (u32)(r * SP_ROW + u4 * 16);
            sts_v4u32(sb + AH_OFF + off, vh.x, vh.y, vh.z, vh.w);
            sts_v4u32(sb + AL_OFF + off, vl.x, vl.y, vl.z, vl.w);
        }
        // B chunk: 64 rows x 8 uint4
#pragma unroll
        for (int it = 0; it < 2; ++it) {
            int f = tid + it * 256;
            int n = f >> 3, u4 = f & 7;
            size_t gi = (size_t)(nb * 64 + n) * (K / 2) + ch * 32 + u4 * 4;
            uint4 vh = *(const uint4*)(Bh_img + gi);
            uint4 vl = *(const uint4*)(Bl_img + gi);
            u32 off = (u32)(n * SP_ROW + u4 * 16);
            sts_v4u32(sb + BH_OFF + off, vh.x, vh.y, vh.z, vh.w);
            sts_v4u32(sb + BL_OFF + off, vl.x, vl.y, vl.z, vl.w);
        }
        __syncthreads();

        int row_off = ((lane >> 3) & 1) * 8 + (lane & 7);
        int khalf = (lane >> 4) * 8;
#pragma unroll
        for (int ks = 0; ks < 4; ++ks) {
            u32 acol = (u32)((ks * 16 + khalf) * 2);
            u32 ah[2][4], al[2][4], bh[2][4], bl[2][4];
#pragma unroll
            for (int mt = 0; mt < 2; ++mt) {
                u32 r = (u32)((wm * 32 + mt * 16 + row_off) * SP_ROW) + acol;
                ldmx4(sb + AH_OFF + r, ah[mt][0], ah[mt][1], ah[mt][2], ah[mt][3]);
                ldmx4(sb + AL_OFF + r, al[mt][0], al[mt][1], al[mt][2], al[mt][3]);
            }
#pragma unroll
            for (int g = 0; g < 2; ++g) {
                u32 r = (u32)((wn * 32 + g * 16 + row_off) * SP_ROW) + acol;
                ldmx4(sb + BH_OFF + r, bh[g][0], bh[g][1], bh[g][2], bh[g][3]);
                ldmx4(sb + BL_OFF + r, bl[g][0], bl[g][1], bl[g][2], bl[g][3]);
            }
#pragma unroll
            for (int mt = 0; mt < 2; ++mt) {
#pragma unroll
                for (int nt = 0; nt < 4; ++nt) {
                    int g = nt >> 1, s = nt & 1;
                    mma_bf16(acc[mt][nt], ah[mt], bh[g][s], bh[g][2 + s]);
                    mma_bf16(acc[mt][nt], ah[mt], bl[g][s], bl[g][2 + s]);
                    mma_bf16(acc[mt][nt], al[mt], bh[g][s], bh[g][2 + s]);
                }
            }
        }
    }

#pragma unroll
    for (int mt = 0; mt < 2; ++mt) {
#pragma unroll
        for (int nt = 0; nt < 4; ++nt) {
            int row = mb * 128 + wm * 32 + mt * 16 + (lane >> 2);
            int col = nb * 64 + wn * 32 + nt * 8 + (lane & 3) * 2;
            float2 bv = *(const float2*)(bias + col);
            float2 o0, o1;
            o0.x = acc[mt][nt][0] + bv.x; o0.y = acc[mt][nt][1] + bv.y;
            o1.x = acc[mt][nt][2] + bv.x; o1.y = acc[mt][nt][3] + bv.y;
            *(float2*)(C + (size_t)row * Gsz + col) = o0;
            *(float2*)(C + (size_t)(row + 8) * Gsz + col) = o1;
        }
    }
}

// ------------------------------ LSTM v6 --------------------------------------
// STORE_ALL=true: h stored as bf16 hi/lo images (for the next layer's GEMM).
// STORE_ALL=false: final h stored fp32 to hout.
template <bool STORE_ALL>
__global__ __launch_bounds__(256, 1) void lstm_kernel(
    const float* __restrict__ pre, const float* __restrict__ whh_t,
    float* __restrict__ hout,
    __nv_bfloat16* __restrict__ ah_img, __nv_bfloat16* __restrict__ al_img) {
    extern __shared__ float smf[];
    u32 sbase = smem_u32(smf);
    int tid = threadIdx.x;
    int j = tid & 127;
    int half = tid >> 7;
    int b0 = blockIdx.x * 4;

    for (int idx = tid * 4; idx < WSM_SLICES * 512; idx += 1024) {
        int s = idx >> 9, col = idx & 511;
        int k = (s >> 5) * 64 + (s & 31);
        *(float4*)(smf + idx) = *(const float4*)(whh_t + (size_t)k * 512 + col);
    }
    u64 wifr[KREGH], wgor[KREGH];
#pragma unroll
    for (int r = 0; r < KREGH; ++r) {
        float4 w = *(const float4*)(whh_t + (size_t)(64 * half + KSMH + r) * 512 + j * 4);
        wifr[r] = pack2(w.x, w.y);
        wgor[r] = pack2(w.z, w.w);
    }

    u32 hd_base = sbase + HD_OFF;
    u32 part_j  = sbase + PART_OFF + j * 16;
    u32 wrow    = sbase + (u32)(KSMH * half) * 2048 + j * 16;
    u32 hd_slot = hd_base + ((j >> 1) * 16) + ((j & 1) * 8);
    int pairbase = 32 * half;

    int bown = half * 2;
    int both = 2 - bown;

    float c[2] = {0.f, 0.f};
#pragma unroll
    for (int q = 0; q < 2; ++q)
        sts_64(hd_slot + (bown + q) * 1024, 0ull);
    __syncthreads();

    size_t poff[2];
#pragma unroll
    for (int q = 0; q < 2; ++q) poff[q] = (size_t)(b0 + bown + q) * Ssz * Gsz;

    float pc[2][4], pn[2][4];
#pragma unroll
    for (int q = 0; q < 2; ++q)
#pragma unroll
        for (int g = 0; g < 4; ++g)
            pc[q][g] = pre[poff[q] + j + g * Hsz];

    for (int t = 0; t < Ssz; ++t) {
        u64 aif[4], ago[4];
#pragma unroll
        for (int b = 0; b < 4; ++b) { aif[b] = 0ull; ago[b] = 0ull; }

        int tn1 = (t + 1 < Ssz) ? (t + 1) : (Ssz - 1);
#pragma unroll
        for (int q = 0; q < 2; ++q)
#pragma unroll
            for (int g = 0; g < 4; ++g)
                pn[q][g] = pre[poff[q] + (size_t)tn1 * Gsz + j + g * Hsz];

#pragma unroll 4
        for (int i = 0; i < 16; ++i) {
            u64 w0i, w0g, w1i, w1g;
            lds_v2(wrow + (u32)(2 * i) * 2048,     w0i, w0g);
            lds_v2(wrow + (u32)(2 * i + 1) * 2048, w1i, w1g);
#pragma unroll
            for (int b = 0; b < 4; ++b) {
                u64 h0, h1;
                lds_v2(hd_base + (u32)((b * 64 + pairbase + i)) * 16, h0, h1);
                aif[b] = ffma2(w0i, h0, aif[b]);
                ago[b] = ffma2(w0g, h0, ago[b]);
                aif[b] = ffma2(w1i, h1, aif[b]);
                ago[b] = ffma2(w1g, h1, ago[b]);
            }
        }
#pragma unroll
        for (int p = 0; p < 16; ++p) {
#pragma unroll
            for (int b = 0; b < 4; ++b) {
                u64 h0, h1;
                lds_v2(hd_base + (u32)(b * 64 + pairbase + 16 + p) * 16, h0, h1);
                aif[b] = ffma2(wifr[2 * p],     h0, aif[b]);
                ago[b] = ffma2(wgor[2 * p],     h0, ago[b]);
                aif[b] = ffma2(wifr[2 * p + 1], h1, aif[b]);
                ago[b] = ffma2(wgor[2 * p + 1], h1, ago[b]);
            }
        }

#pragma unroll
        for (int q = 0; q < 2; ++q) {
            int b = both + q;
            sts_v2(part_j + b * 2048, aif[b], ago[b]);
        }
        __syncthreads();

#pragma unroll
        for (int q = 0; q < 2; ++q) {
            int b = bown + q;
            u64 pif, pgo;
            lds_v2(part_j + b * 2048, pif, pgo);
            u64 sif = addf2(addf2(aif[b], pif), pack2(pc[q][0], pc[q][1]));
            u64 sgo = addf2(addf2(ago[b], pgo), pack2(pc[q][2], pc[q][3]));
            float ip, fp, gp, op;
            unpack2(sif, ip, fp);
            unpack2(sgo, gp, op);
            float ig = sig_fast(ip);
            float fg = sig_fast(fp);
            float gg = tanh_fast(gp);
            float og = sig_fast(op);
            c[q] = fg * c[q] + ig * gg;
            float h = og * tanh_fast(c[q]);
            sts_64(hd_slot + b * 1024, pack2(h, h));
            if (STORE_ALL) {
                size_t ridx = ((size_t)(b0 + b) * Ssz + t) * Hsz + j;
                __nv_bfloat16 hb = __float2bfloat16(h);
                ah_img[ridx] = hb;
                al_img[ridx] = __float2bfloat16(h - __bfloat162float(hb));
            } else if (t == Ssz - 1) {
                hout[(size_t)(b0 + b) * Hsz + j] = h;
            }
        }
#pragma unroll
        for (int q = 0; q < 2; ++q)
#pragma unroll
            for (int g = 0; g < 4; ++g) pc[q][g] = pn[q][g];
        __syncthreads();
    }
}

// ------------------------------- head ---------------------------------------
__global__ void head_kernel(const float* __restrict__ h2, const float* __restrict__ Wlin,
                            const float* __restrict__ blin, float* __restrict__ out) {
    int lane = threadIdx.x & 31;
    int warp = (blockIdx.x * blockDim.x + threadIdx.x) >> 5;
    int nw = (gridDim.x * blockDim.x) >> 5;
    float4 wv = ((const float4*)Wlin)[lane];
    float bl = blin[0];
    for (int b = warp; b < Bsz; b += nw) {
        float4 hv = ((const float4*)(h2 + (size_t)b * Hsz))[lane];
        float s = hv.x * wv.x + hv.y * wv.y + hv.z * wv.z + hv.w * wv.w;
#pragma unroll
        for (int o = 16; o; o >>= 1) s += __shfl_xor_sync(0xFFFFFFFFu, s, o);
        if (lane == 0) out[b] = s + bl;
    }
}

// ------------------------------ launcher ------------------------------------
extern "C" void kernel_launch(void* const* d_in, const int* in_sizes, int n_in,
                              void* d_out, int out_size) {
    const float* x    = (const float*)d_in[0];
    const float* Wih0 = (const float*)d_in[1];
    const float* Whh0 = (const float*)d_in[2];
    const float* bih0 = (const float*)d_in[3];
    const float* bhh0 = (const float*)d_in[4];
    const float* Wih1 = (const float*)d_in[5];
    const float* Whh1 = (const float*)d_in[6];
    const float* bih1 = (const float*)d_in[7];
    const float* bhh1 = (const float*)d_in[8];
    const float* Wlin = (const float*)d_in[9];
    const float* blin = (const float*)d_in[10];
    float* out = (float*)d_out;

    static bool attr_done = false;
    if (!attr_done) {
        cudaFuncSetAttribute(gemm_mma_kernel<Dsz>, cudaFuncAttributeMaxDynamicSharedMemorySize, GEMM_SMEM);
        cudaFuncSetAttribute(gemm_mma_kernel<Hsz>, cudaFuncAttributeMaxDynamicSharedMemorySize, GEMM_SMEM);
        cudaFuncSetAttribute(lstm_kernel<true>,  cudaFuncAttributeMaxDynamicSharedMemorySize, LSTM6_SMEM);
        cudaFuncSetAttribute(lstm_kernel<false>, cudaFuncAttributeMaxDynamicSharedMemorySize, LSTM6_SMEM);
        attr_done = true;
    }

    void *p_pre, *p_h2, *p_whh, *p_bias;
    void *p_b0h, *p_b0l, *p_b1h, *p_b1l;
    void *p_a0h, *p_a0l, *p_a1h, *p_a1l;
    cudaGetSymbolAddress(&p_pre,  g_pre);
    cudaGetSymbolAddress(&p_h2,   g_h2last);
    cudaGetSymbolAddress(&p_whh,  g_whh_t);
    cudaGetSymbolAddress(&p_bias, g_bias);
    cudaGetSymbolAddress(&p_b0h,  g_b0h);
    cudaGetSymbolAddress(&p_b0l,  g_b0l);
    cudaGetSymbolAddress(&p_b1h,  g_b1h);
    cudaGetSymbolAddress(&p_b1l,  g_b1l);
    cudaGetSymbolAddress(&p_a0h,  g_a0h);
    cudaGetSymbolAddress(&p_a0l,  g_a0l);
    cudaGetSymbolAddress(&p_a1h,  g_a1h);
    cudaGetSymbolAddress(&p_a1l,  g_a1l);

    prep_kernel<<<256, 512>>>(x, Wih0, Whh0, bih0, bhh0, Wih1, Whh1, bih1, bhh1);

    dim3 ggrid(Gsz / 64, Bsz * Ssz / 128);   // x = nb (8), y = mb (2048)

    gemm_mma_kernel<Dsz><<<ggrid, 256, GEMM_SMEM>>>(
        (const u32*)p_a0h, (const u32*)p_a0l,
        (const u32*)p_b0h, (const u32*)p_b0l,
        (const float*)p_bias, (float*)p_pre);

    lstm_kernel<true><<<Bsz / 4, 256, LSTM6_SMEM>>>(
        (const float*)p_pre, (const float*)p_whh, nullptr,
        (__nv_bfloat16*)p_a1h, (__nv_bfloat16*)p_a1l);

    gemm_mma_kernel<Hsz><<<ggrid, 256, GEMM_SMEM>>>(
        (const u32*)p_a1h, (const u32*)p_a1l,
        (const u32*)p_b1h, (const u32*)p_b1l,
        (const float*)p_bias + Gsz, (float*)p_pre);

    lstm_kernel<false><<<Bsz / 4, 256, LSTM6_SMEM>>>(
        (const float*)p_pre, (const float*)p_whh + Hsz * Gsz, (float*)p_h2,
        nullptr, nullptr);

    head_kernel<<<8, 256>>>((const float*)p_h2, Wlin, blin, out);
}

// round 15
// speedup vs baseline: 1.0662x; 1.0662x over previous
#include <cuda_runtime.h>
#include <cuda_bf16.h>

#define Bsz 512
#define Ssz 512
#define Dsz 64
#define Hsz 128
#define Gsz 512

// ---- LSTM v6 smem layout (bytes) ----
#define KSMH 32
#define KREGH 32
#define WSM_SLICES 64
#define HD_OFF   (WSM_SLICES*2048)       // 131072
#define PART_OFF (HD_OFF + 4096)
#define LSTM6_SMEM (PART_OFF + 8192)     // 143360

// ---- MMA GEMM smem: tile 128x64, images padded rows of 144B ----
#define SP_ROW 144
#define AH_OFF 0
#define AL_OFF 18432
#define BH_OFF 36864
#define BL_OFF 46080
#define GEMM_SMEM 55296

typedef unsigned long long u64;
typedef unsigned int u32;

__device__ float g_pre[(size_t)Bsz * Ssz * Gsz];
__device__ float g_h1[(size_t)Bsz * Ssz * Hsz];
__device__ float g_h2last[Bsz * Hsz];
__device__ float g_whh_t[2 * Hsz * Gsz];
__device__ float g_bias[2 * Gsz];
__device__ u32 g_b0h[512 * 32], g_b0l[512 * 32];   // layer0 K=64
__device__ u32 g_b1h[512 * 64], g_b1l[512 * 64];   // layer1 K=128

__device__ __forceinline__ u64 pack2(float x, float y) {
    u64 r; asm("mov.b64 %0, {%1,%2};" : "=l"(r) : "f"(x), "f"(y)); return r;
}
__device__ __forceinline__ void unpack2(u64 v, float &x, float &y) {
    asm("mov.b64 {%0,%1}, %2;" : "=f"(x), "=f"(y) : "l"(v));
}
__device__ __forceinline__ u64 ffma2(u64 a, u64 b, u64 c) {
    u64 d; asm("fma.rn.f32x2 %0, %1, %2, %3;" : "=l"(d) : "l"(a), "l"(b), "l"(c));
    return d;
}
__device__ __forceinline__ u64 addf2(u64 a, u64 b) {
    u64 d; asm("add.rn.f32x2 %0, %1, %2;" : "=l"(d) : "l"(a), "l"(b));
    return d;
}
__device__ __forceinline__ u32 smem_u32(const void* p) {
    u32 a; asm("{ .reg .u64 t; cvta.to.shared.u64 t, %1; cvt.u32.u64 %0, t; }" : "=r"(a) : "l"(p));
    return a;
}
__device__ __forceinline__ void lds_v2(u32 a, u64 &x, u64 &y) {
    asm volatile("ld.shared.v2.u64 {%0,%1}, [%2];" : "=l"(x), "=l"(y) : "r"(a));
}
__device__ __forceinline__ u64 lds_64(u32 a) {
    u64 x; asm volatile("ld.shared.u64 %0, [%1];" : "=l"(x) : "r"(a)); return x;
}
__device__ __forceinline__ void sts_v2(u32 a, u64 x, u64 y) {
    asm volatile("st.shared.v2.u64 [%0], {%1,%2};" :: "r"(a), "l"(x), "l"(y));
}
__device__ __forceinline__ void sts_64(u32 a, u64 x) {
    asm volatile("st.shared.u64 [%0], %1;" :: "r"(a), "l"(x));
}
__device__ __forceinline__ void sts_v2u32(u32 a, u32 x, u32 y) {
    asm volatile("st.shared.v2.u32 [%0], {%1,%2};" :: "r"(a), "r"(x), "r"(y));
}
__device__ __forceinline__ void sts_v4u32(u32 a, u32 x, u32 y, u32 z, u32 w) {
    asm volatile("st.shared.v4.u32 [%0], {%1,%2,%3,%4};" :: "r"(a), "r"(x), "r"(y), "r"(z), "r"(w));
}
__device__ __forceinline__ float tanh_fast(float x) {
    float y; asm("tanh.approx.f32 %0, %1;" : "=f"(y) : "f"(x)); return y;
}
__device__ __forceinline__ float sig_fast(float x) {
    return fmaf(tanh_fast(0.5f * x), 0.5f, 0.5f);
}
__device__ __forceinline__ void ldmx4(u32 addr, u32 &r0, u32 &r1, u32 &r2, u32 &r3) {
    asm volatile("ldmatrix.sync.aligned.m8n8.x4.shared.b16 {%0,%1,%2,%3}, [%4];"
                 : "=r"(r0), "=r"(r1), "=r"(r2), "=r"(r3) : "r"(addr));
}
__device__ __forceinline__ void mma_bf16(float* c, const u32* a, u32 b0, u32 b1) {
    asm volatile(
        "mma.sync.aligned.m16n8k16.row.col.f32.bf16.bf16.f32 "
        "{%0,%1,%2,%3}, {%4,%5,%6,%7}, {%8,%9}, {%0,%1,%2,%3};"
        : "+f"(c[0]), "+f"(c[1]), "+f"(c[2]), "+f"(c[3])
        : "r"(a[0]), "r"(a[1]), "r"(a[2]), "r"(a[3]), "r"(b0), "r"(b1));
}
__device__ __forceinline__ void bf16split(float v0, float v1, u32 &hi, u32 &lo) {
    __nv_bfloat16 h0 = __float2bfloat16(v0);
    __nv_bfloat16 h1 = __float2bfloat16(v1);
    float r0 = v0 - __bfloat162float(h0);
    float r1 = v1 - __bfloat162float(h1);
    __nv_bfloat162 hp; hp.x = h0; hp.y = h1;
    __nv_bfloat162 lp; lp.x = __float2bfloat16(r0); lp.y = __float2bfloat16(r1);
    hi = *reinterpret_cast<u32*>(&hp);
    lo = *reinterpret_cast<u32*>(&lp);
}

// --------------------------------- prep -------------------------------------
__global__ void prep_kernel(const float* __restrict__ Wih0, const float* __restrict__ Whh0,
                            const float* __restrict__ bih0, const float* __restrict__ bhh0,
                            const float* __restrict__ Wih1, const float* __restrict__ Whh1,
                            const float* __restrict__ bih1, const float* __restrict__ bhh1) {
    int tid = blockIdx.x * blockDim.x + threadIdx.x;
    int nt  = gridDim.x * blockDim.x;
    for (int idx = tid; idx < Hsz * Gsz; idx += nt) {
        int k = idx >> 9;
        int jg = idx & 511;
        int j = jg >> 2, g = jg & 3;
        g_whh_t[idx]             = Whh0[(g * Hsz + j) * Hsz + k];
        g_whh_t[Hsz * Gsz + idx] = Whh1[(g * Hsz + j) * Hsz + k];
        if (idx < Gsz) {
            g_bias[idx]       = bih0[idx] + bhh0[idx];
            g_bias[Gsz + idx] = bih1[idx] + bhh1[idx];
        }
    }
    for (int i = tid; i < 512 * 32; i += nt) {
        int n = i >> 5, kp = i & 31;
        u32 hi, lo;
        bf16split(Wih0[n * 64 + 2 * kp], Wih0[n * 64 + 2 * kp + 1], hi, lo);
        g_b0h[i] = hi; g_b0l[i] = lo;
    }
    for (int i = tid; i < 512 * 64; i += nt) {
        int n = i >> 6, kp = i & 63;
        u32 hi, lo;
        bf16split(Wih1[n * 128 + 2 * kp], Wih1[n * 128 + 2 * kp + 1], hi, lo);
        g_b1h[i] = hi; g_b1l[i] = lo;
    }
}

// ---------------- mma.sync pre GEMM: tile 128x64, 256 thr, 2 CTAs/SM ---------
// grid: x = nb (N/64), y = mb (BS/128) -> CTAs sharing an A tile run
// concurrently, so A's fp32 re-reads hit L2 instead of DRAM.
template <int K>
__global__ __launch_bounds__(256, 2) void gemm_mma_kernel(
    const float* __restrict__ A, const u32* __restrict__ Bh_img,
    const u32* __restrict__ Bl_img, const float* __restrict__ bias,
    float* __restrict__ C) {
    extern __shared__ char smc[];
    u32 sb = smem_u32(smc);
    int tid = threadIdx.x, lane = tid & 31, wid = tid >> 5;
    int wm = wid & 3, wn = wid >> 2;          // wn in {0,1}
    int nb = blockIdx.x, mb = blockIdx.y;

    float acc[2][4][4];
#pragma unroll
    for (int mt = 0; mt < 2; ++mt)
#pragma unroll
        for (int nt = 0; nt < 4; ++nt)
#pragma unroll
            for (int e = 0; e < 4; ++e) acc[mt][nt][e] = 0.f;

    const int NCH = K / 64;
#pragma unroll
    for (int ch = 0; ch < NCH; ++ch) {
        if (ch) __syncthreads();
        // A chunk: 128 rows x 64 k, fp32 -> hi/lo bf16
        const float* Ag = A + (size_t)mb * 128 * K + ch * 64;
#pragma unroll
        for (int it = 0; it < 8; ++it) {
            int f = tid + it * 256;
            int r = f >> 4, c4 = (f & 15) * 4;
            float4 v = *(const float4*)(Ag + (size_t)r * K + c4);
            u32 h0, l0, h1, l1;
            bf16split(v.x, v.y, h0, l0);
            bf16split(v.z, v.w, h1, l1);
            u32 off = (u32)(r * SP_ROW + c4 * 2);
            sts_v2u32(sb + AH_OFF + off, h0, h1);
            sts_v2u32(sb + AL_OFF + off, l0, l1);
        }
        // B chunk: 64 rows x 8 uint4 (pre-split images)
#pragma unroll
        for (int it = 0; it < 2; ++it) {
            int f = tid + it * 256;
            int n = f >> 3, u4 = f & 7;
            size_t gi = (size_t)(nb * 64 + n) * (K / 2) + ch * 32 + u4 * 4;
            uint4 vh = *(const uint4*)(Bh_img + gi);
            uint4 vl = *(const uint4*)(Bl_img + gi);
            u32 off = (u32)(n * SP_ROW + u4 * 16);
            sts_v4u32(sb + BH_OFF + off, vh.x, vh.y, vh.z, vh.w);
            sts_v4u32(sb + BL_OFF + off, vl.x, vl.y, vl.z, vl.w);
        }
        __syncthreads();

        int row_off = ((lane >> 3) & 1) * 8 + (lane & 7);
        int khalf = (lane >> 4) * 8;
#pragma unroll
        for (int ks = 0; ks < 4; ++ks) {
            u32 acol = (u32)((ks * 16 + khalf) * 2);
            u32 ah[2][4], al[2][4], bh[2][4], bl[2][4];
#pragma unroll
            for (int mt = 0; mt < 2; ++mt) {
                u32 r = (u32)((wm * 32 + mt * 16 + row_off) * SP_ROW) + acol;
                ldmx4(sb + AH_OFF + r, ah[mt][0], ah[mt][1], ah[mt][2], ah[mt][3]);
                ldmx4(sb + AL_OFF + r, al[mt][0], al[mt][1], al[mt][2], al[mt][3]);
            }
#pragma unroll
            for (int g = 0; g < 2; ++g) {
                u32 r = (u32)((wn * 32 + g * 16 + row_off) * SP_ROW) + acol;
                ldmx4(sb + BH_OFF + r, bh[g][0], bh[g][1], bh[g][2], bh[g][3]);
                ldmx4(sb + BL_OFF + r, bl[g][0], bl[g][1], bl[g][2], bl[g][3]);
            }
#pragma unroll
            for (int mt = 0; mt < 2; ++mt) {
#pragma unroll
                for (int nt = 0; nt < 4; ++nt) {
                    int g = nt >> 1, s = nt & 1;
                    mma_bf16(acc[mt][nt], ah[mt], bh[g][s], bh[g][2 + s]);
                    mma_bf16(acc[mt][nt], ah[mt], bl[g][s], bl[g][2 + s]);
                    mma_bf16(acc[mt][nt], al[mt], bh[g][s], bh[g][2 + s]);
                }
            }
        }
    }

    // epilogue
#pragma unroll
    for (int mt = 0; mt < 2; ++mt) {
#pragma unroll
        for (int nt = 0; nt < 4; ++nt) {
            int row = mb * 128 + wm * 32 + mt * 16 + (lane >> 2);
            int col = nb * 64 + wn * 32 + nt * 8 + (lane & 3) * 2;
            float2 bv = *(const float2*)(bias + col);
            float2 o0, o1;
            o0.x = acc[mt][nt][0] + bv.x; o0.y = acc[mt][nt][1] + bv.y;
            o1.x = acc[mt][nt][2] + bv.x; o1.y = acc[mt][nt][3] + bv.y;
            *(float2*)(C + (size_t)row * Gsz + col) = o0;
            *(float2*)(C + (size_t)(row + 8) * Gsz + col) = o1;
        }
    }
}

// ------------------------------ LSTM v6 (frozen, at roofline) ----------------
template <bool STORE_ALL>
__global__ __launch_bounds__(256, 1) void lstm_kernel(
    const float* __restrict__ pre, const float* __restrict__ whh_t,
    float* __restrict__ hout) {
    extern __shared__ float smf[];
    u32 sbase = smem_u32(smf);
    int tid = threadIdx.x;
    int j = tid & 127;
    int half = tid >> 7;
    int b0 = blockIdx.x * 4;

    for (int idx = tid * 4; idx < WSM_SLICES * 512; idx += 1024) {
        int s = idx >> 9, col = idx & 511;
        int k = (s >> 5) * 64 + (s & 31);
        *(float4*)(smf + idx) = *(const float4*)(whh_t + (size_t)k * 512 + col);
    }
    u64 wifr[KREGH], wgor[KREGH];
#pragma unroll
    for (int r = 0; r < KREGH; ++r) {
        float4 w = *(const float4*)(whh_t + (size_t)(64 * half + KSMH + r) * 512 + j * 4);
        wifr[r] = pack2(w.x, w.y);
        wgor[r] = pack2(w.z, w.w);
    }

    u32 hd_base = sbase + HD_OFF;
    u32 part_j  = sbase + PART_OFF + j * 16;
    u32 wrow    = sbase + (u32)(KSMH * half) * 2048 + j * 16;
    u32 hd_slot = hd_base + ((j >> 1) * 16) + ((j & 1) * 8);
    int pairbase = 32 * half;

    int bown = half * 2;
    int both = 2 - bown;

    float c[2] = {0.f, 0.f};
#pragma unroll
    for (int q = 0; q < 2; ++q)
        sts_64(hd_slot + (bown + q) * 1024, 0ull);
    __syncthreads();

    size_t poff[2];
#pragma unroll
    for (int q = 0; q < 2; ++q) poff[q] = (size_t)(b0 + bown + q) * Ssz * Gsz;

    float pc[2][4], pn[2][4];
#pragma unroll
    for (int q = 0; q < 2; ++q)
#pragma unroll
        for (int g = 0; g < 4; ++g)
            pc[q][g] = pre[poff[q] + j + g * Hsz];

    for (int t = 0; t < Ssz; ++t) {
        u64 aif[4], ago[4];
#pragma unroll
        for (int b = 0; b < 4; ++b) { aif[b] = 0ull; ago[b] = 0ull; }

        int tn1 = (t + 1 < Ssz) ? (t + 1) : (Ssz - 1);
#pragma unroll
        for (int q = 0; q < 2; ++q)
#pragma unroll
            for (int g = 0; g < 4; ++g)
                pn[q][g] = pre[poff[q] + (size_t)tn1 * Gsz + j + g * Hsz];

#pragma unroll 4
        for (int i = 0; i < 16; ++i) {
            u64 w0i, w0g, w1i, w1g;
            lds_v2(wrow + (u32)(2 * i) * 2048,     w0i, w0g);
            lds_v2(wrow + (u32)(2 * i + 1) * 2048, w1i, w1g);
#pragma unroll
            for (int b = 0; b < 4; ++b) {
                u64 h0, h1;
                lds_v2(hd_base + (u32)((b * 64 + pairbase + i)) * 16, h0, h1);
                aif[b] = ffma2(w0i, h0, aif[b]);
                ago[b] = ffma2(w0g, h0, ago[b]);
                aif[b] = ffma2(w1i, h1, aif[b]);
                ago[b] = ffma2(w1g, h1, ago[b]);
            }
        }
#pragma unroll
        for (int p = 0; p < 16; ++p) {
#pragma unroll
            for (int b = 0; b < 4; ++b) {
                u64 h0, h1;
                lds_v2(hd_base + (u32)(b * 64 + pairbase + 16 + p) * 16, h0, h1);
                aif[b] = ffma2(wifr[2 * p],     h0, aif[b]);
                ago[b] = ffma2(wgor[2 * p],     h0, ago[b]);
                aif[b] = ffma2(wifr[2 * p + 1], h1, aif[b]);
                ago[b] = ffma2(wgor[2 * p + 1], h1, ago[b]);
            }
        }

#pragma unroll
        for (int q = 0; q < 2; ++q) {
            int b = both + q;
            sts_v2(part_j + b * 2048, aif[b], ago[b]);
        }
        __syncthreads();

#pragma unroll
        for (int q = 0; q < 2; ++q) {
            int b = bown + q;
            u64 pif, pgo;
            lds_v2(part_j + b * 2048, pif, pgo);
            u64 sif = addf2(addf2(aif[b], pif), pack2(pc[q][0], pc[q][1]));
            u64 sgo = addf2(addf2(ago[b], pgo), pack2(pc[q][2], pc[q][3]));
            float ip, fp, gp, op;
            unpack2(sif, ip, fp);
            unpack2(sgo, gp, op);
            float ig = sig_fast(ip);
            float fg = sig_fast(fp);
            float gg = tanh_fast(gp);
            float og = sig_fast(op);
            c[q] = fg * c[q] + ig * gg;
            float h = og * tanh_fast(c[q]);
            sts_64(hd_slot + b * 1024, pack2(h, h));
            if (STORE_ALL) {
                hout[((size_t)(b0 + b) * Ssz + t) * Hsz + j] = h;
            } else if (t == Ssz - 1) {
                hout[(size_t)(b0 + b) * Hsz + j] = h;
            }
        }
#pragma unroll
        for (int q = 0; q < 2; ++q)
#pragma unroll
            for (int g = 0; g < 4; ++g) pc[q][g] = pn[q][g];
        __syncthreads();
    }
}

// ------------------------------- head ---------------------------------------
__global__ void head_kernel(const float* __restrict__ h2, const float* __restrict__ Wlin,
                            const float* __restrict__ blin, float* __restrict__ out) {
    int lane = threadIdx.x & 31;
    int warp = (blockIdx.x * blockDim.x + threadIdx.x) >> 5;
    int nw = (gridDim.x * blockDim.x) >> 5;
    float4 wv = ((const float4*)Wlin)[lane];
    float bl = blin[0];
    for (int b = warp; b < Bsz; b += nw) {
        float4 hv = ((const float4*)(h2 + (size_t)b * Hsz))[lane];
        float s = hv.x * wv.x + hv.y * wv.y + hv.z * wv.z + hv.w * wv.w;
#pragma unroll
        for (int o = 16; o; o >>= 1) s += __shfl_xor_sync(0xFFFFFFFFu, s, o);
        if (lane == 0) out[b] = s + bl;
    }
}

// ------------------------------ launcher ------------------------------------
extern "C" void kernel_launch(void* const* d_in, const int* in_sizes, int n_in,
                              void* d_out, int out_size) {
    const float* x    = (const float*)d_in[0];
    const float* Wih0 = (const float*)d_in[1];
    const float* Whh0 = (const float*)d_in[2];
    const float* bih0 = (const float*)d_in[3];
    const float* bhh0 = (const float*)d_in[4];
    const float* Wih1 = (const float*)d_in[5];
    const float* Whh1 = (const float*)d_in[6];
    const float* bih1 = (const float*)d_in[7];
    const float* bhh1 = (const float*)d_in[8];
    const float* Wlin = (const float*)d_in[9];
    const float* blin = (const float*)d_in[10];
    float* out = (float*)d_out;

    static bool attr_done = false;
    if (!attr_done) {
        cudaFuncSetAttribute(gemm_mma_kernel<Dsz>, cudaFuncAttributeMaxDynamicSharedMemorySize, GEMM_SMEM);
        cudaFuncSetAttribute(gemm_mma_kernel<Hsz>, cudaFuncAttributeMaxDynamicSharedMemorySize, GEMM_SMEM);
        cudaFuncSetAttribute(lstm_kernel<true>,  cudaFuncAttributeMaxDynamicSharedMemorySize, LSTM6_SMEM);
        cudaFuncSetAttribute(lstm_kernel<false>, cudaFuncAttributeMaxDynamicSharedMemorySize, LSTM6_SMEM);
        attr_done = true;
    }

    void *p_pre, *p_h1, *p_h2, *p_whh, *p_bias, *p_b0h, *p_b0l, *p_b1h, *p_b1l;
    cudaGetSymbolAddress(&p_pre,  g_pre);
    cudaGetSymbolAddress(&p_h1,   g_h1);
    cudaGetSymbolAddress(&p_h2,   g_h2last);
    cudaGetSymbolAddress(&p_whh,  g_whh_t);
    cudaGetSymbolAddress(&p_bias, g_bias);
    cudaGetSymbolAddress(&p_b0h,  g_b0h);
    cudaGetSymbolAddress(&p_b0l,  g_b0l);
    cudaGetSymbolAddress(&p_b1h,  g_b1h);
    cudaGetSymbolAddress(&p_b1l,  g_b1l);

    prep_kernel<<<128, 512>>>(Wih0, Whh0, bih0, bhh0, Wih1, Whh1, bih1, bhh1);

    dim3 ggrid(Gsz / 64, Bsz * Ssz / 128);   // x = nb (8), y = mb (2048)

    gemm_mma_kernel<Dsz><<<ggrid, 256, GEMM_SMEM>>>(
        x, (const u32*)p_b0h, (const u32*)p_b0l,
        (const float*)p_bias, (float*)p_pre);

    lstm_kernel<true><<<Bsz / 4, 256, LSTM6_SMEM>>>(
        (const float*)p_pre, (const float*)p_whh, (float*)p_h1);

    gemm_mma_kernel<Hsz><<<ggrid, 256, GEMM_SMEM>>>(
        (const float*)p_h1, (const u32*)p_b1h, (const u32*)p_b1l,
        (const float*)p_bias + Gsz, (float*)p_pre);

    lstm_kernel<false><<<Bsz / 4, 256, LSTM6_SMEM>>>(
        (const float*)p_pre, (const float*)p_whh + Hsz * Gsz, (float*)p_h2);

    head_kernel<<<8, 256>>>((const float*)p_h2, Wlin, blin, out);
}